// round 5
// baseline (speedup 1.0000x reference)
#include <cuda_runtime.h>

// out[h1,w1,c1,h2,w2,c2] = g^(|dh|+|dw|+|dc|) * (1 + spec_pe[c1,c2]*mean[h1,w1,c1]) * decay[c1]
// mean[h1,w1,c1] = Sh[h1]*Sw[w1]*Sc[c1] / (H*W*C), separable geometric sums.
// H=W=32, C=8. Output: 1024 * 65536 floats = 268.4 MB, pure write-bound.
//
// R5 change vs R4 (= R1 best, ncu 41.66us): 256-bit stores (st.global.v8.b32,
// sm_103a arch feature). One thread now writes a full 8-float c2-row (32B),
// so each warp store instruction covers a contiguous 1KB span -> half the
// store instructions / L1 wavefronts. Everything else identical to R4.

#define GAMMA 0.9f

__device__ __forceinline__ void stg256(float* p, float x0, float x1, float x2, float x3,
                                       float x4, float x5, float x6, float x7) {
    asm volatile("st.global.v8.b32 [%0], {%1,%2,%3,%4,%5,%6,%7,%8};"
                 :: "l"(p),
                    "r"(__float_as_uint(x0)), "r"(__float_as_uint(x1)),
                    "r"(__float_as_uint(x2)), "r"(__float_as_uint(x3)),
                    "r"(__float_as_uint(x4)), "r"(__float_as_uint(x5)),
                    "r"(__float_as_uint(x6)), "r"(__float_as_uint(x7))
                 : "memory");
}

__global__ __launch_bounds__(256) void mrp3d_kernel(const float* __restrict__ decay,
                                                    const float* __restrict__ spec_pe,
                                                    float* __restrict__ out) {
    __shared__ float sPow[40];    // gamma^d, d = 0..39 (max needed: 31)
    __shared__ float4 sCoef[16];  // fused coef [c1][c2]: decay*(1+spec*mean)*g^|c1-c2|

    const int h1 = blockIdx.x >> 5;
    const int w1 = blockIdx.x & 31;
    const int t  = threadIdx.x;

    // Build gamma^d table (iterative product; few-ulp error, fine for 1e-3 tol)
    if (t < 40) {
        float p = 1.0f;
        for (int i = 0; i < t; ++i) p *= GAMMA;
        sPow[t] = p;
    }
    __syncthreads();

    // Build fused 8x8 coefficient table for this (h1,w1)
    if (t < 64) {
        const int c1 = t >> 3;
        const int c2 = t & 7;
        float Sh = 0.0f, Sw = 0.0f, Sc = 0.0f;
        #pragma unroll
        for (int j = 0; j < 32; ++j) {
            Sh += sPow[abs(h1 - j)];
            Sw += sPow[abs(w1 - j)];
        }
        #pragma unroll
        for (int j = 0; j < 8; ++j) Sc += sPow[abs(c1 - j)];
        const float mean = Sh * Sw * Sc * (1.0f / 8192.0f);
        const float coef = decay[c1] * (1.0f + spec_pe[c1 * 8 + c2] * mean) * sPow[abs(c1 - c2)];
        reinterpret_cast<float*>(sCoef)[t] = coef;
    }
    __syncthreads();

    // Output slice for this (h1,w1): 65536 floats, contiguous.
    float* __restrict__ outb = out + (size_t)blockIdx.x * 65536;

    // One thread per (h2,w2) c2-row (8 floats = 32B = one STG.256).
    // t covers w2 = t&31, h2base = t>>5 (0..7); h2 = h2base + 8*it, it in [0,4).
    const int w2     = t & 31;
    const int h2base = t >> 5;
    const float sW   = sPow[abs(w1 - w2)];

    #pragma unroll
    for (int c1 = 0; c1 < 8; ++c1) {
        const float4 cfLo = sCoef[(c1 << 1) | 0];
        const float4 cfHi = sCoef[(c1 << 1) | 1];
        float* outc = outb + c1 * 8192;
        #pragma unroll
        for (int it = 0; it < 4; ++it) {
            const int h2 = h2base + (it << 3);
            const float s = sPow[abs(h1 - h2)] * sW;
            float* p = outc + ((h2 << 5) | w2) * 8;
            stg256(p, s * cfLo.x, s * cfLo.y, s * cfLo.z, s * cfLo.w,
                      s * cfHi.x, s * cfHi.y, s * cfHi.z, s * cfHi.w);
        }
    }
}

extern "C" void kernel_launch(void* const* d_in, const int* in_sizes, int n_in,
                              void* d_out, int out_size) {
    // Inputs: x (unused, 524288 elems), decay (8), spec_pe (64) — identify by size.
    const float* decay   = nullptr;
    const float* spec_pe = nullptr;
    for (int i = 0; i < n_in; ++i) {
        if (in_sizes[i] == 8)       decay   = (const float*)d_in[i];
        else if (in_sizes[i] == 64) spec_pe = (const float*)d_in[i];
    }
    mrp3d_kernel<<<1024, 256>>>(decay, spec_pe, (float*)d_out);
}